// round 14
// baseline (speedup 1.0000x reference)
#include <cuda_runtime.h>
#include <cuda_fp16.h>
#include <cstdint>
#include <math.h>

// Problem constants
#define Bb 8
#define Nn 4096
#define Cc 256
#define Hh 8
#define Dd 32
#define HID 1024
#define Mrows (Bb * Nn)            // 32768
#define ROWSZ ((size_t)Mrows * Cc) // 8388608

// ---------------- scratch (device globals; no allocations allowed) ---------
__device__ __half g_xlnh[ROWSZ];
__device__ __half g_slnh[ROWSZ];
__device__ __half g_xh[ROWSZ];
__device__ __half g_sh[ROWSZ];
__device__ __half g_qkvh[(size_t)Mrows * 3 * Cc];
__device__ __half g_attnpreh[ROWSZ];
__device__ __half g_attnprojh[ROWSZ];
__device__ __half g_updateh[ROWSZ];
__device__ __half g_hlnh[ROWSZ];
__device__ __half g_fc1h[(size_t)Mrows * HID];
__device__ float  g_kv[Bb * Hh * Dd * Dd];
// fp16 weights, concatenated (offsets in halves)
#define WOFF_QKVI 0
#define WOFF_QKVS 196608
#define WOFF_PROJ 393216
#define WOFF_GATE 458752
#define WOFF_FC1  589824
#define WOFF_FC2  851968
#define WTOTAL    1114112
__device__ __half g_wh[WTOTAL];

// ---------------- misc helpers ----------------------------------------------
__device__ __forceinline__ float2 block_sum2(float a, float b, float* sm) {
    #pragma unroll
    for (int o = 16; o > 0; o >>= 1) {
        a += __shfl_down_sync(0xffffffffu, a, o);
        b += __shfl_down_sync(0xffffffffu, b, o);
    }
    int w = threadIdx.x >> 5, l = threadIdx.x & 31;
    if (l == 0) { sm[w] = a; sm[8 + w] = b; }
    __syncthreads();
    if (w == 0) {
        a = sm[l & 7]; b = sm[8 + (l & 7)];
        #pragma unroll
        for (int o = 4; o > 0; o >>= 1) {
            a += __shfl_down_sync(0xffffffffu, a, o);
            b += __shfl_down_sync(0xffffffffu, b, o);
        }
        if (l == 0) { sm[16] = a; sm[17] = b; }
    }
    __syncthreads();
    return make_float2(sm[16], sm[17]);
}

__device__ __forceinline__ float phi_fn(float x) {
    return x > 0.f ? x + 1.f : expf(x);
}

__device__ __forceinline__ uint32_t smem_to_u32(const void* p) {
    uint32_t a;
    asm("{ .reg .u64 t; cvta.to.shared.u64 t, %1; cvt.u32.u64 %0, t; }"
        : "=r"(a) : "l"(p));
    return a;
}

__device__ __forceinline__ void cpasync16(uint32_t smem_addr, const void* gptr) {
    asm volatile("cp.async.cg.shared.global [%0], [%1], 16;"
        :: "r"(smem_addr), "l"(gptr) : "memory");
}
__device__ __forceinline__ void cpasync_commit() {
    asm volatile("cp.async.commit_group;" ::: "memory");
}
template <int N>
__device__ __forceinline__ void cpasync_wait() {
    asm volatile("cp.async.wait_group %0;" :: "n"(N) : "memory");
}

// fp16 m16n8k16 mma: D (f32x4) += A(f16x2 x4) @ B(f16x2 x2)
__device__ __forceinline__ void mma_f16(
    float& c0, float& c1, float& c2, float& c3,
    uint32_t a0, uint32_t a1, uint32_t a2, uint32_t a3,
    uint32_t b0, uint32_t b1)
{
    asm volatile(
        "mma.sync.aligned.m16n8k16.row.col.f32.f16.f16.f32 "
        "{%0,%1,%2,%3}, {%4,%5,%6,%7}, {%8,%9}, {%0,%1,%2,%3};"
        : "+f"(c0), "+f"(c1), "+f"(c2), "+f"(c3)
        : "r"(a0), "r"(a1), "r"(a2), "r"(a3), "r"(b0), "r"(b1));
}

// ------- all weights fp32 -> fp16 + zero g_kv, single kernel -----------------
__global__ void __launch_bounds__(256) w2h_all_kernel(
    const float* __restrict__ qkvi, const float* __restrict__ qkvs,
    const float* __restrict__ proj, const float* __restrict__ gate,
    const float* __restrict__ fc1,  const float* __restrict__ fc2)
{
    int i = blockIdx.x * 256 + threadIdx.x;   // float4 index, 278528 weights
    if (i >= 278528) {
        int idx = i - 278528;                 // 16384 threads zero g_kv (65536 f)
        *reinterpret_cast<float4*>(&g_kv[idx * 4]) = make_float4(0.f, 0.f, 0.f, 0.f);
        return;
    }
    const float* src; int local; int woff;
    if      (i < 49152)  { src = qkvi; local = i;          woff = WOFF_QKVI; }
    else if (i < 98304)  { src = qkvs; local = i - 49152;  woff = WOFF_QKVS; }
    else if (i < 114688) { src = proj; local = i - 98304;  woff = WOFF_PROJ; }
    else if (i < 147456) { src = gate; local = i - 114688; woff = WOFF_GATE; }
    else if (i < 212992) { src = fc1;  local = i - 147456; woff = WOFF_FC1;  }
    else                 { src = fc2;  local = i - 212992; woff = WOFF_FC2;  }
    float4 v = reinterpret_cast<const float4*>(src)[local];
    __half2* d = reinterpret_cast<__half2*>(&g_wh[woff]) + 2 * local;
    d[0] = __floats2half2_rn(v.x, v.y);
    d[1] = __floats2half2_rn(v.z, v.w);
}

// ---------------- kernel 1: LN1(x+pos), LN2(prev), fp16 copies ---------------
__global__ void __launch_bounds__(256) ln_pre_kernel(
    const float* __restrict__ input_, const float* __restrict__ prev,
    const float* __restrict__ pos,
    const float* __restrict__ w1, const float* __restrict__ b1,
    const float* __restrict__ w2, const float* __restrict__ b2)
{
    __shared__ float sm[32];
    int r = blockIdx.x;
    int c = threadIdx.x;
    int n = r & (Nn - 1);
    size_t o = (size_t)r * Cc + c;

    float xin = input_[o];
    float x = xin + pos[(size_t)n * Cc + c];
    g_xh[o] = __float2half_rn(xin);
    float2 ss = block_sum2(x, x * x, sm);
    float mu = ss.x * (1.f / Cc);
    float var = ss.y * (1.f / Cc) - mu * mu;
    g_xlnh[o] = __float2half_rn((x - mu) * rsqrtf(var + 1e-5f) * w1[c] + b1[c]);

    float s = prev[o];
    g_sh[o] = __float2half_rn(s);
    ss = block_sum2(s, s * s, sm);
    mu = ss.x * (1.f / Cc);
    var = ss.y * (1.f / Cc) - mu * mu;
    g_slnh[o] = __float2half_rn((s - mu) * rsqrtf(var + 1e-5f) * w2[c] + b2[c]);
}

// ---------------- fp16 mma GEMM: C = sum_p A_p @ W_p^T (+bias,act) ----------
// Block tile 128x128, warp grid 2x4 (warp tile 64x32), K chunk = 32 halves.
// smem m-major [row][KPh=40] fp16 (conflict-free frags), 3-stage cp.async,
// single __syncthreads per chunk, 2 CTAs/SM.
// act: 0 none, 1 gelu, 2 sigmoid, 3 phi on cols<512 (qkv). resid: C += v.
// outhalf: fp16 store.
#define GBM 128
#define GBN 128
#define GKC 32
#define KPh 40
#define HBUF (GBM * KPh)                   // 5120 halves per buffer
#define NSTG 3
#define GEMM_SMEM_BYTES (2 * NSTG * HBUF * 2)  // 61440 B

__global__ void __launch_bounds__(256, 2) mma_gemm_kernel(
    const __half* __restrict__ A0, const __half* __restrict__ A1,
    const __half* __restrict__ W0, const __half* __restrict__ W1,
    const float* __restrict__ bias, void* __restrict__ Cmat,
    int Nt, int K, int ldw, int act, int resid, int outhalf)
{
    extern __shared__ __half smh[];
    const uint32_t sbase = smem_to_u32(smh);
    const int tid = threadIdx.x;
    const int bm = blockIdx.y * GBM;
    const int bn = blockIdx.x * GBN;
    const int wid = tid >> 5, lane = tid & 31;
    const int gid = lane >> 2, tig = lane & 3;
    const int wm = (wid >> 2) * 64;
    const int wn = (wid & 3) * 32;

    float acc[4][4][4];
    #pragma unroll
    for (int mt = 0; mt < 4; mt++)
        #pragma unroll
        for (int nt = 0; nt < 4; nt++)
            #pragma unroll
            for (int q = 0; q < 4; q++) acc[mt][nt][q] = 0.f;

    const int kchunks = K / GKC;
    const int npairs = (A1 != nullptr) ? 2 : 1;
    const int nchunks = kchunks * npairs;

    auto issue = [&](int c) {
        const int buf = c % NSTG;
        const int p = c / kchunks;
        const int k0 = (c - p * kchunks) * GKC;
        const __half* __restrict__ A = p ? A1 : A0;
        const __half* __restrict__ W = p ? W1 : W0;
        #pragma unroll
        for (int i = 0; i < 2; i++) {
            int f = tid + i * 256;
            int row = f >> 2, seg = f & 3;
            uint32_t da = sbase + (uint32_t)((buf * HBUF + row * KPh + seg * 8) * 2);
            cpasync16(da, &A[(size_t)(bm + row) * K + k0 + seg * 8]);
            uint32_t db = sbase + (uint32_t)(((NSTG + buf) * HBUF + row * KPh + seg * 8) * 2);
            cpasync16(db, &W[(size_t)(bn + row) * ldw + k0 + seg * 8]);
        }
        cpasync_commit();
    };

    issue(0);
    if (nchunks > 1) issue(1);

    for (int c = 0; c < nchunks; c++) {
        if (c + 1 < nchunks) {
            cpasync_wait<1>();
        } else {
            cpasync_wait<0>();
        }
        __syncthreads();
        // Safe: writes buffer (c+2)%NSTG == (c-1)%NSTG, whose readers (chunk
        // c-1 compute) all passed the barrier above.
        if (c + 2 < nchunks) issue(c + 2);

        const int buf = c % NSTG;
        const __half* Asm = &smh[buf * HBUF];
        const __half* Bsm = &smh[(NSTG + buf) * HBUF];

        #pragma unroll
        for (int ks = 0; ks < 2; ks++) {
            const int kb = ks * 16;
            uint32_t af[4][4], bf[4][2];
            #pragma unroll
            for (int mt = 0; mt < 4; mt++) {
                int m0 = wm + mt * 16 + gid;
                af[mt][0] = *reinterpret_cast<const uint32_t*>(&Asm[m0 * KPh + kb + 2 * tig]);
                af[mt][1] = *reinterpret_cast<const uint32_t*>(&Asm[(m0 + 8) * KPh + kb + 2 * tig]);
                af[mt][2] = *reinterpret_cast<const uint32_t*>(&Asm[m0 * KPh + kb + 8 + 2 * tig]);
                af[mt][3] = *reinterpret_cast<const uint32_t*>(&Asm[(m0 + 8) * KPh + kb + 8 + 2 * tig]);
            }
            #pragma unroll
            for (int nt = 0; nt < 4; nt++) {
                int n0 = wn + nt * 8 + gid;
                bf[nt][0] = *reinterpret_cast<const uint32_t*>(&Bsm[n0 * KPh + kb + 2 * tig]);
                bf[nt][1] = *reinterpret_cast<const uint32_t*>(&Bsm[n0 * KPh + kb + 8 + 2 * tig]);
            }
            #pragma unroll
            for (int mt = 0; mt < 4; mt++)
                #pragma unroll
                for (int nt = 0; nt < 4; nt++)
                    mma_f16(acc[mt][nt][0], acc[mt][nt][1],
                            acc[mt][nt][2], acc[mt][nt][3],
                            af[mt][0], af[mt][1], af[mt][2], af[mt][3],
                            bf[nt][0], bf[nt][1]);
        }
    }

    // epilogue
    #pragma unroll
    for (int mt = 0; mt < 4; mt++) {
        #pragma unroll
        for (int nt = 0; nt < 4; nt++) {
            int row0 = bm + wm + mt * 16 + gid;
            int col0 = bn + wn + nt * 8 + tig * 2;
            #pragma unroll
            for (int half = 0; half < 2; half++) {
                int r = row0 + half * 8;
                float v0 = acc[mt][nt][half * 2 + 0];
                float v1 = acc[mt][nt][half * 2 + 1];
                if (bias) { v0 += bias[col0]; v1 += bias[col0 + 1]; }
                if (act == 1) {
                    v0 = 0.5f * v0 * (1.f + erff(v0 * 0.70710678118654752f));
                    v1 = 0.5f * v1 * (1.f + erff(v1 * 0.70710678118654752f));
                } else if (act == 2) {
                    v0 = 1.f / (1.f + expf(-v0));
                    v1 = 1.f / (1.f + expf(-v1));
                } else if (act == 3) {
                    if (col0 < 2 * Cc) { v0 = phi_fn(v0); v1 = phi_fn(v1); }
                }
                size_t o = (size_t)r * Nt + col0;
                if (outhalf) {
                    *reinterpret_cast<__half2*>(&((__half*)Cmat)[o]) =
                        __floats2half2_rn(v0, v1);
                } else {
                    float* Cf = (float*)Cmat;
                    if (resid) {
                        float2 old = *reinterpret_cast<const float2*>(&Cf[o]);
                        v0 += old.x; v1 += old.y;
                    }
                    *reinterpret_cast<float2*>(&Cf[o]) = make_float2(v0, v1);
                }
            }
        }
    }
}

// ------- kv = sum_n phi_k[n,d] * v[n,e] (phi already applied in qkv) ---------
__global__ void __launch_bounds__(256) kv_kernel() {
    const int bh = blockIdx.x;
    const int chunk = blockIdx.y;
    const int b = bh >> 3, h = bh & 7;
    __shared__ float ks[32][36];
    __shared__ float vs[32][36];
    const int t = threadIdx.x;
    const int d = t >> 3;
    const int e0 = (t & 7) * 4;
    float acc[4] = {0.f, 0.f, 0.f, 0.f};
    const int nbase = chunk * 256;

    for (int nb = 0; nb < 256; nb += 32) {
        #pragma unroll
        for (int i = 0; i < 2; i++) {
            int idx = t + i * 256;
            int row = idx >> 4, cp = (idx & 15) * 2;
            size_t base = ((size_t)(b * Nn + nbase + nb + row)) * (3 * Cc) + h * Dd + cp;
            float2 kf = __half22float2(*reinterpret_cast<const __half2*>(&g_qkvh[base + Cc]));
            float2 vf = __half22float2(*reinterpret_cast<const __half2*>(&g_qkvh[base + 2 * Cc]));
            *reinterpret_cast<float2*>(&ks[row][cp]) = kf;
            *reinterpret_cast<float2*>(&vs[row][cp]) = vf;
        }
        __syncthreads();
        #pragma unroll
        for (int nn = 0; nn < 32; nn++) {
            float kd = ks[nn][d];
            float4 vv = *reinterpret_cast<const float4*>(&vs[nn][e0]);
            acc[0] = fmaf(kd, vv.x, acc[0]);
            acc[1] = fmaf(kd, vv.y, acc[1]);
            acc[2] = fmaf(kd, vv.z, acc[2]);
            acc[3] = fmaf(kd, vv.w, acc[3]);
        }
        __syncthreads();
    }
    #pragma unroll
    for (int j = 0; j < 4; j++)
        atomicAdd(&g_kv[(size_t)bh * (Dd * Dd) + d * Dd + e0 + j], acc[j]);
}

// ---------------- attn_pre = phi_q @ kv (phi pre-applied, fp16 in/out) -------
__global__ void __launch_bounds__(256) attn_kernel() {
    const int r = blockIdx.x;
    const int b = r >> 12;
    const int c = threadIdx.x;
    __shared__ float pq[Cc];
    pq[c] = __half2float(g_qkvh[(size_t)r * (3 * Cc) + c]);
    __syncthreads();
    const int h = c >> 5, e = c & 31;
    const float* kvp = &g_kv[((size_t)(b * Hh + h)) * (Dd * Dd) + e];
    const float* pqh = &pq[h * Dd];
    float s = 0.f;
    #pragma unroll
    for (int d2 = 0; d2 < Dd; d2++)
        s = fmaf(pqh[d2], kvp[d2 * Dd], s);
    g_attnpreh[(size_t)r * Cc + c] = __float2half_rn(s);
}

// ------- fused: output_mid, new_state (gate), LN3 (fp16 out) -----------------
__global__ void __launch_bounds__(256) fuse_mid_kernel(
    const float* __restrict__ input_, const float* __restrict__ pos,
    const float* __restrict__ prev,
    const float* __restrict__ w3, const float* __restrict__ b3,
    float* __restrict__ out, float* __restrict__ nstate)
{
    __shared__ float sm[32];
    int r = blockIdx.x;
    int c = threadIdx.x;
    int n = r & (Nn - 1);
    size_t o = (size_t)r * Cc + c;
    float a = __half2float(g_attnprojh[o]);
    float om = input_[o] + pos[(size_t)n * Cc + c] + a;
    out[o] = om;
    float u = __half2float(g_updateh[o]);
    nstate[o] = prev[o] * (1.f - u) + a * u;
    float2 ss = block_sum2(om, om * om, sm);
    float mu = ss.x * (1.f / Cc);
    float var = ss.y * (1.f / Cc) - mu * mu;
    g_hlnh[o] = __float2half_rn((om - mu) * rsqrtf(var + 1e-5f) * w3[c] + b3[c]);
}

// ---------------- launch ----------------------------------------------------
extern "C" void kernel_launch(void* const* d_in, const int* in_sizes, int n_in,
                              void* d_out, int out_size) {
    const float* input_   = (const float*)d_in[0];
    const float* prev     = (const float*)d_in[1];
    const float* pos      = (const float*)d_in[2];
    const float* n1w      = (const float*)d_in[3];
    const float* n1b      = (const float*)d_in[4];
    const float* n2w      = (const float*)d_in[5];
    const float* n2b      = (const float*)d_in[6];
    const float* n3w      = (const float*)d_in[7];
    const float* n3b      = (const float*)d_in[8];
    const float* qkv_iw   = (const float*)d_in[9];
    const float* qkv_sw   = (const float*)d_in[10];
    const float* proj_w   = (const float*)d_in[11];
    const float* proj_b   = (const float*)d_in[12];
    const float* gate_w   = (const float*)d_in[13];
    const float* gate_b   = (const float*)d_in[14];
    const float* fc1_w    = (const float*)d_in[15];
    const float* fc1_b    = (const float*)d_in[16];
    const float* fc2_w    = (const float*)d_in[17];
    const float* fc2_b    = (const float*)d_in[18];

    float* out    = (float*)d_out;
    float* nstate = out + (size_t)out_size / 2;

    __half *p_wh;
    __half *p_xlnh, *p_slnh, *p_xh, *p_sh, *p_qkvh, *p_attnpreh, *p_attnprojh,
           *p_updateh, *p_hlnh, *p_fc1h;
    cudaGetSymbolAddress((void**)&p_wh, g_wh);
    cudaGetSymbolAddress((void**)&p_xlnh, g_xlnh);
    cudaGetSymbolAddress((void**)&p_slnh, g_slnh);
    cudaGetSymbolAddress((void**)&p_xh, g_xh);
    cudaGetSymbolAddress((void**)&p_sh, g_sh);
    cudaGetSymbolAddress((void**)&p_qkvh, g_qkvh);
    cudaGetSymbolAddress((void**)&p_attnpreh, g_attnpreh);
    cudaGetSymbolAddress((void**)&p_attnprojh, g_attnprojh);
    cudaGetSymbolAddress((void**)&p_updateh, g_updateh);
    cudaGetSymbolAddress((void**)&p_hlnh, g_hlnh);
    cudaGetSymbolAddress((void**)&p_fc1h, g_fc1h);

    cudaFuncSetAttribute(mma_gemm_kernel,
                         cudaFuncAttributeMaxDynamicSharedMemorySize,
                         GEMM_SMEM_BYTES);

    // 0) all weights -> fp16 + zero g_kv (one kernel)
    w2h_all_kernel<<<1152, 256>>>(qkv_iw, qkv_sw, proj_w, gate_w, fc1_w, fc2_w);

    // 1) LN1 + LN2 + fp16 copies
    ln_pre_kernel<<<Mrows, 256>>>(input_, prev, pos, n1w, n1b, n2w, n2b);

    // 2) qkv = x_ln @ Wi^T + s_ln @ Ws^T  (phi applied to q,k cols) fp16 out
    mma_gemm_kernel<<<dim3(768 / GBN, Mrows / GBM), 256, GEMM_SMEM_BYTES>>>(
        p_xlnh, p_slnh, p_wh + WOFF_QKVI, p_wh + WOFF_QKVS, nullptr, p_qkvh,
        3 * Cc, Cc, Cc, 3, 0, 1);

    // 3) kv[b,h,d,e]
    kv_kernel<<<dim3(Bb * Hh, 16), 256>>>();

    // 4) attn_pre = phi_q @ kv (fp16 out)
    attn_kernel<<<Mrows, 256>>>();

    // 5) proj (fp16 out)
    mma_gemm_kernel<<<dim3(Cc / GBN, Mrows / GBM), 256, GEMM_SMEM_BYTES>>>(
        p_attnpreh, nullptr, p_wh + WOFF_PROJ, nullptr, proj_b, p_attnprojh,
        Cc, Cc, Cc, 0, 0, 1);

    // 6) gate: update = sigmoid([input_, prev] @ gate_w^T + gate_b) (fp16 out)
    mma_gemm_kernel<<<dim3(Cc / GBN, Mrows / GBM), 256, GEMM_SMEM_BYTES>>>(
        p_xh, p_sh, p_wh + WOFF_GATE, p_wh + WOFF_GATE + Cc, gate_b, p_updateh,
        Cc, Cc, 2 * Cc, 2, 0, 1);

    // 7) output_mid -> d_out, new_state, LN3 -> g_hlnh
    fuse_mid_kernel<<<Mrows, 256>>>(input_, pos, prev, n3w, n3b, out, nstate);

    // 8) fc1 with exact-gelu epilogue (fp16 out)
    mma_gemm_kernel<<<dim3(HID / GBN, Mrows / GBM), 256, GEMM_SMEM_BYTES>>>(
        p_hlnh, nullptr, p_wh + WOFF_FC1, nullptr, fc1_b, p_fc1h,
        HID, Cc, Cc, 1, 0, 1);

    // 9) fc2, accumulate into output residual (fp32)
    mma_gemm_kernel<<<dim3(Cc / GBN, Mrows / GBM), 256, GEMM_SMEM_BYTES>>>(
        p_fc1h, nullptr, p_wh + WOFF_FC2, nullptr, fc2_b, out,
        Cc, HID, HID, 0, 1, 0);
}

// round 15
// speedup vs baseline: 1.4971x; 1.4971x over previous
#include <cuda_runtime.h>
#include <cuda_fp16.h>
#include <cstdint>
#include <math.h>

// Problem constants
#define Bb 8
#define Nn 4096
#define Cc 256
#define Hh 8
#define Dd 32
#define HID 1024
#define Mrows (Bb * Nn)            // 32768
#define ROWSZ ((size_t)Mrows * Cc) // 8388608

// ---------------- scratch (device globals; no allocations allowed) ---------
__device__ __half g_xlnh[ROWSZ];
__device__ __half g_slnh[ROWSZ];
__device__ __half g_xh[ROWSZ];
__device__ __half g_sh[ROWSZ];
__device__ __half g_qkvh[(size_t)Mrows * 3 * Cc];
__device__ __half g_attnpreh[ROWSZ];
__device__ __half g_attnprojh[ROWSZ];
__device__ __half g_updateh[ROWSZ];
__device__ __half g_hlnh[ROWSZ];
__device__ __half g_fc1h[(size_t)Mrows * HID];
__device__ float  g_kv[Bb * Hh * Dd * Dd];
// fp16 weights, concatenated (offsets in halves)
#define WOFF_QKVI 0
#define WOFF_QKVS 196608
#define WOFF_PROJ 393216
#define WOFF_GATE 458752
#define WOFF_FC1  589824
#define WOFF_FC2  851968
#define WTOTAL    1114112
__device__ __half g_wh[WTOTAL];

// ---------------- misc helpers ----------------------------------------------
__device__ __forceinline__ float2 block_sum2(float a, float b, float* sm) {
    #pragma unroll
    for (int o = 16; o > 0; o >>= 1) {
        a += __shfl_down_sync(0xffffffffu, a, o);
        b += __shfl_down_sync(0xffffffffu, b, o);
    }
    int w = threadIdx.x >> 5, l = threadIdx.x & 31;
    if (l == 0) { sm[w] = a; sm[8 + w] = b; }
    __syncthreads();
    if (w == 0) {
        a = sm[l & 7]; b = sm[8 + (l & 7)];
        #pragma unroll
        for (int o = 4; o > 0; o >>= 1) {
            a += __shfl_down_sync(0xffffffffu, a, o);
            b += __shfl_down_sync(0xffffffffu, b, o);
        }
        if (l == 0) { sm[16] = a; sm[17] = b; }
    }
    __syncthreads();
    return make_float2(sm[16], sm[17]);
}

__device__ __forceinline__ float phi_fn(float x) {
    return x > 0.f ? x + 1.f : expf(x);
}

__device__ __forceinline__ uint32_t smem_to_u32(const void* p) {
    uint32_t a;
    asm("{ .reg .u64 t; cvta.to.shared.u64 t, %1; cvt.u32.u64 %0, t; }"
        : "=r"(a) : "l"(p));
    return a;
}

__device__ __forceinline__ void cpasync16(uint32_t smem_addr, const void* gptr) {
    asm volatile("cp.async.cg.shared.global [%0], [%1], 16;"
        :: "r"(smem_addr), "l"(gptr) : "memory");
}
__device__ __forceinline__ void cpasync_commit() {
    asm volatile("cp.async.commit_group;" ::: "memory");
}
template <int N>
__device__ __forceinline__ void cpasync_wait() {
    asm volatile("cp.async.wait_group %0;" :: "n"(N) : "memory");
}

// fp16 m16n8k16 mma: D (f32x4) += A(f16x2 x4) @ B(f16x2 x2)
__device__ __forceinline__ void mma_f16(
    float& c0, float& c1, float& c2, float& c3,
    uint32_t a0, uint32_t a1, uint32_t a2, uint32_t a3,
    uint32_t b0, uint32_t b1)
{
    asm volatile(
        "mma.sync.aligned.m16n8k16.row.col.f32.f16.f16.f32 "
        "{%0,%1,%2,%3}, {%4,%5,%6,%7}, {%8,%9}, {%0,%1,%2,%3};"
        : "+f"(c0), "+f"(c1), "+f"(c2), "+f"(c3)
        : "r"(a0), "r"(a1), "r"(a2), "r"(a3), "r"(b0), "r"(b1));
}

// ------- all weights fp32 -> fp16 + zero g_kv, single kernel -----------------
__global__ void __launch_bounds__(256) w2h_all_kernel(
    const float* __restrict__ qkvi, const float* __restrict__ qkvs,
    const float* __restrict__ proj, const float* __restrict__ gate,
    const float* __restrict__ fc1,  const float* __restrict__ fc2)
{
    int i = blockIdx.x * 256 + threadIdx.x;   // float4 index, 278528 weights
    if (i >= 278528) {
        int idx = i - 278528;                 // 16384 threads zero g_kv (65536 f)
        *reinterpret_cast<float4*>(&g_kv[idx * 4]) = make_float4(0.f, 0.f, 0.f, 0.f);
        return;
    }
    const float* src; int local; int woff;
    if      (i < 49152)  { src = qkvi; local = i;          woff = WOFF_QKVI; }
    else if (i < 98304)  { src = qkvs; local = i - 49152;  woff = WOFF_QKVS; }
    else if (i < 114688) { src = proj; local = i - 98304;  woff = WOFF_PROJ; }
    else if (i < 147456) { src = gate; local = i - 114688; woff = WOFF_GATE; }
    else if (i < 212992) { src = fc1;  local = i - 147456; woff = WOFF_FC1;  }
    else                 { src = fc2;  local = i - 212992; woff = WOFF_FC2;  }
    float4 v = reinterpret_cast<const float4*>(src)[local];
    __half2* d = reinterpret_cast<__half2*>(&g_wh[woff]) + 2 * local;
    d[0] = __floats2half2_rn(v.x, v.y);
    d[1] = __floats2half2_rn(v.z, v.w);
}

// ---------------- kernel 1: LN1(x+pos), LN2(prev), fp16 copies ---------------
__global__ void __launch_bounds__(256) ln_pre_kernel(
    const float* __restrict__ input_, const float* __restrict__ prev,
    const float* __restrict__ pos,
    const float* __restrict__ w1, const float* __restrict__ b1,
    const float* __restrict__ w2, const float* __restrict__ b2)
{
    __shared__ float sm[32];
    int r = blockIdx.x;
    int c = threadIdx.x;
    int n = r & (Nn - 1);
    size_t o = (size_t)r * Cc + c;

    float xin = input_[o];
    float x = xin + pos[(size_t)n * Cc + c];
    g_xh[o] = __float2half_rn(xin);
    float2 ss = block_sum2(x, x * x, sm);
    float mu = ss.x * (1.f / Cc);
    float var = ss.y * (1.f / Cc) - mu * mu;
    g_xlnh[o] = __float2half_rn((x - mu) * rsqrtf(var + 1e-5f) * w1[c] + b1[c]);

    float s = prev[o];
    g_sh[o] = __float2half_rn(s);
    ss = block_sum2(s, s * s, sm);
    mu = ss.x * (1.f / Cc);
    var = ss.y * (1.f / Cc) - mu * mu;
    g_slnh[o] = __float2half_rn((s - mu) * rsqrtf(var + 1e-5f) * w2[c] + b2[c]);
}

// ---------------- fp16 mma GEMM: C = sum_p A_p @ W_p^T (+bias,act) ----------
// Block tile 128x128, warp grid 2x4 (warp tile 64x32), K chunk = 32 halves.
// smem m-major [row][KPh=40] fp16 (conflict-free frags), 3-stage cp.async,
// single __syncthreads per chunk, 2 CTAs/SM.
// act: 0 none, 1 gelu, 2 sigmoid, 3 phi on cols<512 (qkv). resid: C += v.
// outhalf: fp16 store.
#define GBM 128
#define GBN 128
#define GKC 32
#define KPh 40
#define HBUF (GBM * KPh)                   // 5120 halves per buffer
#define NSTG 3
#define GEMM_SMEM_BYTES (2 * NSTG * HBUF * 2)  // 61440 B

__global__ void __launch_bounds__(256, 2) mma_gemm_kernel(
    const __half* __restrict__ A0, const __half* __restrict__ A1,
    const __half* __restrict__ W0, const __half* __restrict__ W1,
    const float* __restrict__ bias, void* __restrict__ Cmat,
    int Nt, int K, int ldw, int act, int resid, int outhalf)
{
    extern __shared__ __half smh[];
    const uint32_t sbase = smem_to_u32(smh);
    const int tid = threadIdx.x;
    const int bm = blockIdx.y * GBM;
    const int bn = blockIdx.x * GBN;
    const int wid = tid >> 5, lane = tid & 31;
    const int gid = lane >> 2, tig = lane & 3;
    const int wm = (wid >> 2) * 64;
    const int wn = (wid & 3) * 32;

    float acc[4][4][4];
    #pragma unroll
    for (int mt = 0; mt < 4; mt++)
        #pragma unroll
        for (int nt = 0; nt < 4; nt++)
            #pragma unroll
            for (int q = 0; q < 4; q++) acc[mt][nt][q] = 0.f;

    const int kchunks = K / GKC;
    const int npairs = (A1 != nullptr) ? 2 : 1;
    const int nchunks = kchunks * npairs;

    auto issue = [&](int c) {
        const int buf = c % NSTG;
        const int p = c / kchunks;
        const int k0 = (c - p * kchunks) * GKC;
        const __half* __restrict__ A = p ? A1 : A0;
        const __half* __restrict__ W = p ? W1 : W0;
        #pragma unroll
        for (int i = 0; i < 2; i++) {
            int f = tid + i * 256;
            int row = f >> 2, seg = f & 3;
            uint32_t da = sbase + (uint32_t)((buf * HBUF + row * KPh + seg * 8) * 2);
            cpasync16(da, &A[(size_t)(bm + row) * K + k0 + seg * 8]);
            uint32_t db = sbase + (uint32_t)(((NSTG + buf) * HBUF + row * KPh + seg * 8) * 2);
            cpasync16(db, &W[(size_t)(bn + row) * ldw + k0 + seg * 8]);
        }
        cpasync_commit();
    };

    issue(0);
    if (nchunks > 1) issue(1);

    for (int c = 0; c < nchunks; c++) {
        if (c + 1 < nchunks) {
            cpasync_wait<1>();
        } else {
            cpasync_wait<0>();
        }
        __syncthreads();
        // Safe: writes buffer (c+2)%NSTG == (c-1)%NSTG, whose readers (chunk
        // c-1 compute) all passed the barrier above.
        if (c + 2 < nchunks) issue(c + 2);

        const int buf = c % NSTG;
        const __half* Asm = &smh[buf * HBUF];
        const __half* Bsm = &smh[(NSTG + buf) * HBUF];

        #pragma unroll
        for (int ks = 0; ks < 2; ks++) {
            const int kb = ks * 16;
            uint32_t af[4][4], bf[4][2];
            #pragma unroll
            for (int mt = 0; mt < 4; mt++) {
                int m0 = wm + mt * 16 + gid;
                af[mt][0] = *reinterpret_cast<const uint32_t*>(&Asm[m0 * KPh + kb + 2 * tig]);
                af[mt][1] = *reinterpret_cast<const uint32_t*>(&Asm[(m0 + 8) * KPh + kb + 2 * tig]);
                af[mt][2] = *reinterpret_cast<const uint32_t*>(&Asm[m0 * KPh + kb + 8 + 2 * tig]);
                af[mt][3] = *reinterpret_cast<const uint32_t*>(&Asm[(m0 + 8) * KPh + kb + 8 + 2 * tig]);
            }
            #pragma unroll
            for (int nt = 0; nt < 4; nt++) {
                int n0 = wn + nt * 8 + gid;
                bf[nt][0] = *reinterpret_cast<const uint32_t*>(&Bsm[n0 * KPh + kb + 2 * tig]);
                bf[nt][1] = *reinterpret_cast<const uint32_t*>(&Bsm[n0 * KPh + kb + 8 + 2 * tig]);
            }
            #pragma unroll
            for (int mt = 0; mt < 4; mt++)
                #pragma unroll
                for (int nt = 0; nt < 4; nt++)
                    mma_f16(acc[mt][nt][0], acc[mt][nt][1],
                            acc[mt][nt][2], acc[mt][nt][3],
                            af[mt][0], af[mt][1], af[mt][2], af[mt][3],
                            bf[nt][0], bf[nt][1]);
        }
    }

    // epilogue
    #pragma unroll
    for (int mt = 0; mt < 4; mt++) {
        #pragma unroll
        for (int nt = 0; nt < 4; nt++) {
            int row0 = bm + wm + mt * 16 + gid;
            int col0 = bn + wn + nt * 8 + tig * 2;
            #pragma unroll
            for (int half = 0; half < 2; half++) {
                int r = row0 + half * 8;
                float v0 = acc[mt][nt][half * 2 + 0];
                float v1 = acc[mt][nt][half * 2 + 1];
                if (bias) { v0 += bias[col0]; v1 += bias[col0 + 1]; }
                if (act == 1) {
                    v0 = 0.5f * v0 * (1.f + erff(v0 * 0.70710678118654752f));
                    v1 = 0.5f * v1 * (1.f + erff(v1 * 0.70710678118654752f));
                } else if (act == 2) {
                    v0 = 1.f / (1.f + expf(-v0));
                    v1 = 1.f / (1.f + expf(-v1));
                } else if (act == 3) {
                    if (col0 < 2 * Cc) { v0 = phi_fn(v0); v1 = phi_fn(v1); }
                }
                size_t o = (size_t)r * Nt + col0;
                if (outhalf) {
                    *reinterpret_cast<__half2*>(&((__half*)Cmat)[o]) =
                        __floats2half2_rn(v0, v1);
                } else {
                    float* Cf = (float*)Cmat;
                    if (resid) {
                        float2 old = *reinterpret_cast<const float2*>(&Cf[o]);
                        v0 += old.x; v1 += old.y;
                    }
                    *reinterpret_cast<float2*>(&Cf[o]) = make_float2(v0, v1);
                }
            }
        }
    }
}

// ------- kv = sum_n phi_k[n,d] * v[n,e] (phi already applied in qkv) ---------
__global__ void __launch_bounds__(256) kv_kernel() {
    const int bh = blockIdx.x;
    const int chunk = blockIdx.y;
    const int b = bh >> 3, h = bh & 7;
    __shared__ float ks[32][36];
    __shared__ float vs[32][36];
    const int t = threadIdx.x;
    const int d = t >> 3;
    const int e0 = (t & 7) * 4;
    float acc[4] = {0.f, 0.f, 0.f, 0.f};
    const int nbase = chunk * 256;

    for (int nb = 0; nb < 256; nb += 32) {
        #pragma unroll
        for (int i = 0; i < 2; i++) {
            int idx = t + i * 256;
            int row = idx >> 4, cp = (idx & 15) * 2;
            size_t base = ((size_t)(b * Nn + nbase + nb + row)) * (3 * Cc) + h * Dd + cp;
            float2 kf = __half22float2(*reinterpret_cast<const __half2*>(&g_qkvh[base + Cc]));
            float2 vf = __half22float2(*reinterpret_cast<const __half2*>(&g_qkvh[base + 2 * Cc]));
            *reinterpret_cast<float2*>(&ks[row][cp]) = kf;
            *reinterpret_cast<float2*>(&vs[row][cp]) = vf;
        }
        __syncthreads();
        #pragma unroll
        for (int nn = 0; nn < 32; nn++) {
            float kd = ks[nn][d];
            float4 vv = *reinterpret_cast<const float4*>(&vs[nn][e0]);
            acc[0] = fmaf(kd, vv.x, acc[0]);
            acc[1] = fmaf(kd, vv.y, acc[1]);
            acc[2] = fmaf(kd, vv.z, acc[2]);
            acc[3] = fmaf(kd, vv.w, acc[3]);
        }
        __syncthreads();
    }
    #pragma unroll
    for (int j = 0; j < 4; j++)
        atomicAdd(&g_kv[(size_t)bh * (Dd * Dd) + d * Dd + e0 + j], acc[j]);
}

// ---------------- attn_pre = phi_q @ kv (phi pre-applied, fp16 in/out) -------
__global__ void __launch_bounds__(256) attn_kernel() {
    const int r = blockIdx.x;
    const int b = r >> 12;
    const int c = threadIdx.x;
    __shared__ float pq[Cc];
    pq[c] = __half2float(g_qkvh[(size_t)r * (3 * Cc) + c]);
    __syncthreads();
    const int h = c >> 5, e = c & 31;
    const float* kvp = &g_kv[((size_t)(b * Hh + h)) * (Dd * Dd) + e];
    const float* pqh = &pq[h * Dd];
    float s = 0.f;
    #pragma unroll
    for (int d2 = 0; d2 < Dd; d2++)
        s = fmaf(pqh[d2], kvp[d2 * Dd], s);
    g_attnpreh[(size_t)r * Cc + c] = __float2half_rn(s);
}

// ------- fused: output_mid, new_state (gate), LN3 (fp16 out) -----------------
__global__ void __launch_bounds__(256) fuse_mid_kernel(
    const float* __restrict__ input_, const float* __restrict__ pos,
    const float* __restrict__ prev,
    const float* __restrict__ w3, const float* __restrict__ b3,
    float* __restrict__ out, float* __restrict__ nstate)
{
    __shared__ float sm[32];
    int r = blockIdx.x;
    int c = threadIdx.x;
    int n = r & (Nn - 1);
    size_t o = (size_t)r * Cc + c;
    float a = __half2float(g_attnprojh[o]);
    float om = input_[o] + pos[(size_t)n * Cc + c] + a;
    out[o] = om;
    float u = __half2float(g_updateh[o]);
    nstate[o] = prev[o] * (1.f - u) + a * u;
    float2 ss = block_sum2(om, om * om, sm);
    float mu = ss.x * (1.f / Cc);
    float var = ss.y * (1.f / Cc) - mu * mu;
    g_hlnh[o] = __float2half_rn((om - mu) * rsqrtf(var + 1e-5f) * w3[c] + b3[c]);
}

// ---------------- launch ----------------------------------------------------
extern "C" void kernel_launch(void* const* d_in, const int* in_sizes, int n_in,
                              void* d_out, int out_size) {
    const float* input_   = (const float*)d_in[0];
    const float* prev     = (const float*)d_in[1];
    const float* pos      = (const float*)d_in[2];
    const float* n1w      = (const float*)d_in[3];
    const float* n1b      = (const float*)d_in[4];
    const float* n2w      = (const float*)d_in[5];
    const float* n2b      = (const float*)d_in[6];
    const float* n3w      = (const float*)d_in[7];
    const float* n3b      = (const float*)d_in[8];
    const float* qkv_iw   = (const float*)d_in[9];
    const float* qkv_sw   = (const float*)d_in[10];
    const float* proj_w   = (const float*)d_in[11];
    const float* proj_b   = (const float*)d_in[12];
    const float* gate_w   = (const float*)d_in[13];
    const float* gate_b   = (const float*)d_in[14];
    const float* fc1_w    = (const float*)d_in[15];
    const float* fc1_b    = (const float*)d_in[16];
    const float* fc2_w    = (const float*)d_in[17];
    const float* fc2_b    = (const float*)d_in[18];

    float* out    = (float*)d_out;
    float* nstate = out + (size_t)out_size / 2;

    __half *p_wh;
    __half *p_xlnh, *p_slnh, *p_xh, *p_sh, *p_qkvh, *p_attnpreh, *p_attnprojh,
           *p_updateh, *p_hlnh, *p_fc1h;
    cudaGetSymbolAddress((void**)&p_wh, g_wh);
    cudaGetSymbolAddress((void**)&p_xlnh, g_xlnh);
    cudaGetSymbolAddress((void**)&p_slnh, g_slnh);
    cudaGetSymbolAddress((void**)&p_xh, g_xh);
    cudaGetSymbolAddress((void**)&p_sh, g_sh);
    cudaGetSymbolAddress((void**)&p_qkvh, g_qkvh);
    cudaGetSymbolAddress((void**)&p_attnpreh, g_attnpreh);
    cudaGetSymbolAddress((void**)&p_attnprojh, g_attnprojh);
    cudaGetSymbolAddress((void**)&p_updateh, g_updateh);
    cudaGetSymbolAddress((void**)&p_hlnh, g_hlnh);
    cudaGetSymbolAddress((void**)&p_fc1h, g_fc1h);

    cudaFuncSetAttribute(mma_gemm_kernel,
                         cudaFuncAttributeMaxDynamicSharedMemorySize,
                         GEMM_SMEM_BYTES);

    // 0) all weights -> fp16 + zero g_kv (one kernel)
    w2h_all_kernel<<<1152, 256>>>(qkv_iw, qkv_sw, proj_w, gate_w, fc1_w, fc2_w);

    // 1) LN1 + LN2 + fp16 copies
    ln_pre_kernel<<<Mrows, 256>>>(input_, prev, pos, n1w, n1b, n2w, n2b);

    // 2) qkv = x_ln @ Wi^T + s_ln @ Ws^T  (phi applied to q,k cols) fp16 out
    mma_gemm_kernel<<<dim3(768 / GBN, Mrows / GBM), 256, GEMM_SMEM_BYTES>>>(
        p_xlnh, p_slnh, p_wh + WOFF_QKVI, p_wh + WOFF_QKVS, nullptr, p_qkvh,
        3 * Cc, Cc, Cc, 3, 0, 1);

    // 3) kv[b,h,d,e]
    kv_kernel<<<dim3(Bb * Hh, 16), 256>>>();

    // 4) attn_pre = phi_q @ kv (fp16 out)
    attn_kernel<<<Mrows, 256>>>();

    // 5) proj (fp16 out)
    mma_gemm_kernel<<<dim3(Cc / GBN, Mrows / GBM), 256, GEMM_SMEM_BYTES>>>(
        p_attnpreh, nullptr, p_wh + WOFF_PROJ, nullptr, proj_b, p_attnprojh,
        Cc, Cc, Cc, 0, 0, 1);

    // 6) gate: update = sigmoid([input_, prev] @ gate_w^T + gate_b) (fp16 out)
    mma_gemm_kernel<<<dim3(Cc / GBN, Mrows / GBM), 256, GEMM_SMEM_BYTES>>>(
        p_xh, p_sh, p_wh + WOFF_GATE, p_wh + WOFF_GATE + Cc, gate_b, p_updateh,
        Cc, Cc, 2 * Cc, 2, 0, 1);

    // 7) output_mid -> d_out, new_state, LN3 -> g_hlnh
    fuse_mid_kernel<<<Mrows, 256>>>(input_, pos, prev, n3w, n3b, out, nstate);

    // 8) fc1 with exact-gelu epilogue (fp16 out)
    mma_gemm_kernel<<<dim3(HID / GBN, Mrows / GBM), 256, GEMM_SMEM_BYTES>>>(
        p_hlnh, nullptr, p_wh + WOFF_FC1, nullptr, fc1_b, p_fc1h,
        HID, Cc, Cc, 1, 0, 1);

    // 9) fc2, accumulate into output residual (fp32)
    mma_gemm_kernel<<<dim3(Cc / GBN, Mrows / GBM), 256, GEMM_SMEM_BYTES>>>(
        p_fc1h, nullptr, p_wh + WOFF_FC2, nullptr, fc2_b, out,
        Cc, HID, HID, 0, 1, 0);
}

// round 16
// speedup vs baseline: 1.6159x; 1.0793x over previous
#include <cuda_runtime.h>
#include <cuda_fp16.h>
#include <cstdint>
#include <math.h>

// Problem constants
#define Bb 8
#define Nn 4096
#define Cc 256
#define Hh 8
#define Dd 32
#define HID 1024
#define Mrows (Bb * Nn)            // 32768
#define ROWSZ ((size_t)Mrows * Cc) // 8388608

// ---------------- scratch (device globals; no allocations allowed) ---------
__device__ __half g_xlnh[ROWSZ];
__device__ __half g_slnh[ROWSZ];
__device__ __half g_xh[ROWSZ];
__device__ __half g_sh[ROWSZ];
__device__ __half g_qkvh[(size_t)Mrows * 3 * Cc];
__device__ __half g_attnpreh[ROWSZ];
__device__ __half g_attnprojh[ROWSZ];
__device__ __half g_updateh[ROWSZ];
__device__ __half g_hlnh[ROWSZ];
__device__ __half g_fc1h[(size_t)Mrows * HID];
__device__ float  g_kv[Bb * Hh * Dd * Dd];
// fp16 weights, concatenated (offsets in halves)
#define WOFF_QKVI 0
#define WOFF_QKVS 196608
#define WOFF_PROJ 393216
#define WOFF_GATE 458752
#define WOFF_FC1  589824
#define WOFF_FC2  851968
#define WTOTAL    1114112
__device__ __half g_wh[WTOTAL];

// ---------------- misc helpers ----------------------------------------------
__device__ __forceinline__ float phi_fn(float x) {
    return x > 0.f ? x + 1.f : expf(x);
}

__device__ __forceinline__ uint32_t smem_to_u32(const void* p) {
    uint32_t a;
    asm("{ .reg .u64 t; cvta.to.shared.u64 t, %1; cvt.u32.u64 %0, t; }"
        : "=r"(a) : "l"(p));
    return a;
}

__device__ __forceinline__ void cpasync16(uint32_t smem_addr, const void* gptr) {
    asm volatile("cp.async.cg.shared.global [%0], [%1], 16;"
        :: "r"(smem_addr), "l"(gptr) : "memory");
}
__device__ __forceinline__ void cpasync_commit() {
    asm volatile("cp.async.commit_group;" ::: "memory");
}
template <int N>
__device__ __forceinline__ void cpasync_wait() {
    asm volatile("cp.async.wait_group %0;" :: "n"(N) : "memory");
}

// fp16 m16n8k16 mma: D (f32x4) += A(f16x2 x4) @ B(f16x2 x2)
__device__ __forceinline__ void mma_f16(
    float& c0, float& c1, float& c2, float& c3,
    uint32_t a0, uint32_t a1, uint32_t a2, uint32_t a3,
    uint32_t b0, uint32_t b1)
{
    asm volatile(
        "mma.sync.aligned.m16n8k16.row.col.f32.f16.f16.f32 "
        "{%0,%1,%2,%3}, {%4,%5,%6,%7}, {%8,%9}, {%0,%1,%2,%3};"
        : "+f"(c0), "+f"(c1), "+f"(c2), "+f"(c3)
        : "r"(a0), "r"(a1), "r"(a2), "r"(a3), "r"(b0), "r"(b1));
}

// warp butterfly sum of (a,b) -> all lanes
__device__ __forceinline__ float2 warp_sum2(float a, float b) {
    #pragma unroll
    for (int o = 16; o > 0; o >>= 1) {
        a += __shfl_xor_sync(0xffffffffu, a, o);
        b += __shfl_xor_sync(0xffffffffu, b, o);
    }
    return make_float2(a, b);
}

// pack 8 floats -> uint4 of halves
__device__ __forceinline__ uint4 pack8h(const float* v) {
    uint4 u;
    __half2 h0 = __floats2half2_rn(v[0], v[1]);
    __half2 h1 = __floats2half2_rn(v[2], v[3]);
    __half2 h2 = __floats2half2_rn(v[4], v[5]);
    __half2 h3 = __floats2half2_rn(v[6], v[7]);
    u.x = *reinterpret_cast<uint32_t*>(&h0);
    u.y = *reinterpret_cast<uint32_t*>(&h1);
    u.z = *reinterpret_cast<uint32_t*>(&h2);
    u.w = *reinterpret_cast<uint32_t*>(&h3);
    return u;
}
__device__ __forceinline__ void unpack8h(const uint4 u, float* v) {
    const __half2* h = reinterpret_cast<const __half2*>(&u);
    #pragma unroll
    for (int i = 0; i < 4; i++) {
        float2 f = __half22float2(h[i]);
        v[2 * i] = f.x; v[2 * i + 1] = f.y;
    }
}

// ------- all weights fp32 -> fp16 + zero g_kv, single kernel -----------------
__global__ void __launch_bounds__(256) w2h_all_kernel(
    const float* __restrict__ qkvi, const float* __restrict__ qkvs,
    const float* __restrict__ proj, const float* __restrict__ gate,
    const float* __restrict__ fc1,  const float* __restrict__ fc2)
{
    int i = blockIdx.x * 256 + threadIdx.x;   // float4 index, 278528 weights
    if (i >= 278528) {
        int idx = i - 278528;                 // 16384 threads zero g_kv (65536 f)
        *reinterpret_cast<float4*>(&g_kv[idx * 4]) = make_float4(0.f, 0.f, 0.f, 0.f);
        return;
    }
    const float* src; int local; int woff;
    if      (i < 49152)  { src = qkvi; local = i;          woff = WOFF_QKVI; }
    else if (i < 98304)  { src = qkvs; local = i - 49152;  woff = WOFF_QKVS; }
    else if (i < 114688) { src = proj; local = i - 98304;  woff = WOFF_PROJ; }
    else if (i < 147456) { src = gate; local = i - 114688; woff = WOFF_GATE; }
    else if (i < 212992) { src = fc1;  local = i - 147456; woff = WOFF_FC1;  }
    else                 { src = fc2;  local = i - 212992; woff = WOFF_FC2;  }
    float4 v = reinterpret_cast<const float4*>(src)[local];
    __half2* d = reinterpret_cast<__half2*>(&g_wh[woff]) + 2 * local;
    d[0] = __floats2half2_rn(v.x, v.y);
    d[1] = __floats2half2_rn(v.z, v.w);
}

// ---- kernel 1: LN1(x+pos), LN2(prev), fp16 copies — warp per row ------------
__global__ void __launch_bounds__(256) ln_pre_kernel(
    const float* __restrict__ input_, const float* __restrict__ prev,
    const float* __restrict__ pos,
    const float* __restrict__ w1, const float* __restrict__ b1,
    const float* __restrict__ w2, const float* __restrict__ b2)
{
    const int w = threadIdx.x >> 5, lane = threadIdx.x & 31;
    const int r = blockIdx.x * 8 + w;
    const int n = r & (Nn - 1);
    const int c0 = lane * 8;
    const size_t o = (size_t)r * Cc + c0;

    float xv[8], sv[8], wv1[8], bv1[8];
    {
        float4 a = *reinterpret_cast<const float4*>(&input_[o]);
        float4 b = *reinterpret_cast<const float4*>(&input_[o + 4]);
        float4 pa = *reinterpret_cast<const float4*>(&pos[(size_t)n * Cc + c0]);
        float4 pb = *reinterpret_cast<const float4*>(&pos[(size_t)n * Cc + c0 + 4]);
        float xin[8] = {a.x, a.y, a.z, a.w, b.x, b.y, b.z, b.w};
        float pp[8] = {pa.x, pa.y, pa.z, pa.w, pb.x, pb.y, pb.z, pb.w};
        *reinterpret_cast<uint4*>(&g_xh[o]) = pack8h(xin);
        #pragma unroll
        for (int i = 0; i < 8; i++) xv[i] = xin[i] + pp[i];
    }
    {
        float4 a = *reinterpret_cast<const float4*>(&prev[o]);
        float4 b = *reinterpret_cast<const float4*>(&prev[o + 4]);
        sv[0]=a.x; sv[1]=a.y; sv[2]=a.z; sv[3]=a.w;
        sv[4]=b.x; sv[5]=b.y; sv[6]=b.z; sv[7]=b.w;
        float tmp[8];
        #pragma unroll
        for (int i = 0; i < 8; i++) tmp[i] = sv[i];
        *reinterpret_cast<uint4*>(&g_sh[o]) = pack8h(tmp);
    }
    {
        float4 a = *reinterpret_cast<const float4*>(&w1[c0]);
        float4 b = *reinterpret_cast<const float4*>(&w1[c0 + 4]);
        wv1[0]=a.x; wv1[1]=a.y; wv1[2]=a.z; wv1[3]=a.w;
        wv1[4]=b.x; wv1[5]=b.y; wv1[6]=b.z; wv1[7]=b.w;
        a = *reinterpret_cast<const float4*>(&b1[c0]);
        b = *reinterpret_cast<const float4*>(&b1[c0 + 4]);
        bv1[0]=a.x; bv1[1]=a.y; bv1[2]=a.z; bv1[3]=a.w;
        bv1[4]=b.x; bv1[5]=b.y; bv1[6]=b.z; bv1[7]=b.w;
    }

    float s1 = 0.f, s2 = 0.f;
    #pragma unroll
    for (int i = 0; i < 8; i++) { s1 += xv[i]; s2 += xv[i] * xv[i]; }
    float2 ss = warp_sum2(s1, s2);
    float mu = ss.x * (1.f / Cc);
    float rstd = rsqrtf(ss.y * (1.f / Cc) - mu * mu + 1e-5f);
    float outv[8];
    #pragma unroll
    for (int i = 0; i < 8; i++) outv[i] = (xv[i] - mu) * rstd * wv1[i] + bv1[i];
    *reinterpret_cast<uint4*>(&g_xlnh[o]) = pack8h(outv);

    s1 = 0.f; s2 = 0.f;
    #pragma unroll
    for (int i = 0; i < 8; i++) { s1 += sv[i]; s2 += sv[i] * sv[i]; }
    ss = warp_sum2(s1, s2);
    mu = ss.x * (1.f / Cc);
    rstd = rsqrtf(ss.y * (1.f / Cc) - mu * mu + 1e-5f);
    {
        float4 a = *reinterpret_cast<const float4*>(&w2[c0]);
        float4 b = *reinterpret_cast<const float4*>(&w2[c0 + 4]);
        float wv[8] = {a.x, a.y, a.z, a.w, b.x, b.y, b.z, b.w};
        a = *reinterpret_cast<const float4*>(&b2[c0]);
        b = *reinterpret_cast<const float4*>(&b2[c0 + 4]);
        float bv[8] = {a.x, a.y, a.z, a.w, b.x, b.y, b.z, b.w};
        #pragma unroll
        for (int i = 0; i < 8; i++) outv[i] = (sv[i] - mu) * rstd * wv[i] + bv[i];
    }
    *reinterpret_cast<uint4*>(&g_slnh[o]) = pack8h(outv);
}

// ---------------- fp16 mma GEMM: C = sum_p A_p @ W_p^T (+bias,act) ----------
#define GBM 128
#define GBN 128
#define GKC 32
#define KPh 40
#define HBUF (GBM * KPh)
#define NSTG 3
#define GEMM_SMEM_BYTES (2 * NSTG * HBUF * 2)  // 61440 B

__global__ void __launch_bounds__(256, 2) mma_gemm_kernel(
    const __half* __restrict__ A0, const __half* __restrict__ A1,
    const __half* __restrict__ W0, const __half* __restrict__ W1,
    const float* __restrict__ bias, void* __restrict__ Cmat,
    int Nt, int K, int ldw, int act, int resid, int outhalf)
{
    extern __shared__ __half smh[];
    const uint32_t sbase = smem_to_u32(smh);
    const int tid = threadIdx.x;
    const int bm = blockIdx.y * GBM;
    const int bn = blockIdx.x * GBN;
    const int wid = tid >> 5, lane = tid & 31;
    const int gid = lane >> 2, tig = lane & 3;
    const int wm = (wid >> 2) * 64;
    const int wn = (wid & 3) * 32;

    float acc[4][4][4];
    #pragma unroll
    for (int mt = 0; mt < 4; mt++)
        #pragma unroll
        for (int nt = 0; nt < 4; nt++)
            #pragma unroll
            for (int q = 0; q < 4; q++) acc[mt][nt][q] = 0.f;

    const int kchunks = K / GKC;
    const int npairs = (A1 != nullptr) ? 2 : 1;
    const int nchunks = kchunks * npairs;

    auto issue = [&](int c) {
        const int buf = c % NSTG;
        const int p = c / kchunks;
        const int k0 = (c - p * kchunks) * GKC;
        const __half* __restrict__ A = p ? A1 : A0;
        const __half* __restrict__ W = p ? W1 : W0;
        #pragma unroll
        for (int i = 0; i < 2; i++) {
            int f = tid + i * 256;
            int row = f >> 2, seg = f & 3;
            uint32_t da = sbase + (uint32_t)((buf * HBUF + row * KPh + seg * 8) * 2);
            cpasync16(da, &A[(size_t)(bm + row) * K + k0 + seg * 8]);
            uint32_t db = sbase + (uint32_t)(((NSTG + buf) * HBUF + row * KPh + seg * 8) * 2);
            cpasync16(db, &W[(size_t)(bn + row) * ldw + k0 + seg * 8]);
        }
        cpasync_commit();
    };

    issue(0);
    if (nchunks > 1) issue(1);

    for (int c = 0; c < nchunks; c++) {
        if (c + 1 < nchunks) {
            cpasync_wait<1>();
        } else {
            cpasync_wait<0>();
        }
        __syncthreads();
        if (c + 2 < nchunks) issue(c + 2);

        const int buf = c % NSTG;
        const __half* Asm = &smh[buf * HBUF];
        const __half* Bsm = &smh[(NSTG + buf) * HBUF];

        #pragma unroll
        for (int ks = 0; ks < 2; ks++) {
            const int kb = ks * 16;
            uint32_t af[4][4], bf[4][2];
            #pragma unroll
            for (int mt = 0; mt < 4; mt++) {
                int m0 = wm + mt * 16 + gid;
                af[mt][0] = *reinterpret_cast<const uint32_t*>(&Asm[m0 * KPh + kb + 2 * tig]);
                af[mt][1] = *reinterpret_cast<const uint32_t*>(&Asm[(m0 + 8) * KPh + kb + 2 * tig]);
                af[mt][2] = *reinterpret_cast<const uint32_t*>(&Asm[m0 * KPh + kb + 8 + 2 * tig]);
                af[mt][3] = *reinterpret_cast<const uint32_t*>(&Asm[(m0 + 8) * KPh + kb + 8 + 2 * tig]);
            }
            #pragma unroll
            for (int nt = 0; nt < 4; nt++) {
                int n0 = wn + nt * 8 + gid;
                bf[nt][0] = *reinterpret_cast<const uint32_t*>(&Bsm[n0 * KPh + kb + 2 * tig]);
                bf[nt][1] = *reinterpret_cast<const uint32_t*>(&Bsm[n0 * KPh + kb + 8 + 2 * tig]);
            }
            #pragma unroll
            for (int mt = 0; mt < 4; mt++)
                #pragma unroll
                for (int nt = 0; nt < 4; nt++)
                    mma_f16(acc[mt][nt][0], acc[mt][nt][1],
                            acc[mt][nt][2], acc[mt][nt][3],
                            af[mt][0], af[mt][1], af[mt][2], af[mt][3],
                            bf[nt][0], bf[nt][1]);
        }
    }

    // epilogue
    #pragma unroll
    for (int mt = 0; mt < 4; mt++) {
        #pragma unroll
        for (int nt = 0; nt < 4; nt++) {
            int row0 = bm + wm + mt * 16 + gid;
            int col0 = bn + wn + nt * 8 + tig * 2;
            #pragma unroll
            for (int half = 0; half < 2; half++) {
                int r = row0 + half * 8;
                float v0 = acc[mt][nt][half * 2 + 0];
                float v1 = acc[mt][nt][half * 2 + 1];
                if (bias) { v0 += bias[col0]; v1 += bias[col0 + 1]; }
                if (act == 1) {
                    v0 = 0.5f * v0 * (1.f + erff(v0 * 0.70710678118654752f));
                    v1 = 0.5f * v1 * (1.f + erff(v1 * 0.70710678118654752f));
                } else if (act == 2) {
                    v0 = 1.f / (1.f + expf(-v0));
                    v1 = 1.f / (1.f + expf(-v1));
                } else if (act == 3) {
                    if (col0 < 2 * Cc) { v0 = phi_fn(v0); v1 = phi_fn(v1); }
                }
                size_t o = (size_t)r * Nt + col0;
                if (outhalf) {
                    *reinterpret_cast<__half2*>(&((__half*)Cmat)[o]) =
                        __floats2half2_rn(v0, v1);
                } else {
                    float* Cf = (float*)Cmat;
                    if (resid) {
                        float2 old = *reinterpret_cast<const float2*>(&Cf[o]);
                        v0 += old.x; v1 += old.y;
                    }
                    *reinterpret_cast<float2*>(&Cf[o]) = make_float2(v0, v1);
                }
            }
        }
    }
}

// ------- kv = sum_n phi_k[n,d] * v[n,e] (phi already applied in qkv) ---------
__global__ void __launch_bounds__(256) kv_kernel() {
    const int bh = blockIdx.x;
    const int chunk = blockIdx.y;
    const int b = bh >> 3, h = bh & 7;
    __shared__ float ks[32][36];
    __shared__ float vs[32][36];
    const int t = threadIdx.x;
    const int d = t >> 3;
    const int e0 = (t & 7) * 4;
    float acc[4] = {0.f, 0.f, 0.f, 0.f};
    const int nbase = chunk * 256;

    for (int nb = 0; nb < 256; nb += 32) {
        #pragma unroll
        for (int i = 0; i < 2; i++) {
            int idx = t + i * 256;
            int row = idx >> 4, cp = (idx & 15) * 2;
            size_t base = ((size_t)(b * Nn + nbase + nb + row)) * (3 * Cc) + h * Dd + cp;
            float2 kf = __half22float2(*reinterpret_cast<const __half2*>(&g_qkvh[base + Cc]));
            float2 vf = __half22float2(*reinterpret_cast<const __half2*>(&g_qkvh[base + 2 * Cc]));
            *reinterpret_cast<float2*>(&ks[row][cp]) = kf;
            *reinterpret_cast<float2*>(&vs[row][cp]) = vf;
        }
        __syncthreads();
        #pragma unroll
        for (int nn = 0; nn < 32; nn++) {
            float kd = ks[nn][d];
            float4 vv = *reinterpret_cast<const float4*>(&vs[nn][e0]);
            acc[0] = fmaf(kd, vv.x, acc[0]);
            acc[1] = fmaf(kd, vv.y, acc[1]);
            acc[2] = fmaf(kd, vv.z, acc[2]);
            acc[3] = fmaf(kd, vv.w, acc[3]);
        }
        __syncthreads();
    }
    #pragma unroll
    for (int j = 0; j < 4; j++)
        atomicAdd(&g_kv[(size_t)bh * (Dd * Dd) + d * Dd + e0 + j], acc[j]);
}

// ---- attn_pre = phi_q @ kv — warp per (row, head), shuffle broadcast --------
__global__ void __launch_bounds__(256) attn_kernel() {
    const int r = blockIdx.x;
    const int b = r >> 12;
    const int h = threadIdx.x >> 5, lane = threadIdx.x & 31;
    float pqv = __half2float(g_qkvh[(size_t)r * (3 * Cc) + h * Dd + lane]);
    const float* kvp = &g_kv[((size_t)(b * Hh + h)) * (Dd * Dd)];
    float s = 0.f;
    #pragma unroll
    for (int d2 = 0; d2 < Dd; d2++)
        s = fmaf(__shfl_sync(0xffffffffu, pqv, d2), kvp[d2 * Dd + lane], s);
    g_attnpreh[(size_t)r * Cc + h * Dd + lane] = __float2half_rn(s);
}

// ------- fused: output_mid, new_state, LN3 — warp per row --------------------
__global__ void __launch_bounds__(256) fuse_mid_kernel(
    const float* __restrict__ input_, const float* __restrict__ pos,
    const float* __restrict__ prev,
    const float* __restrict__ w3, const float* __restrict__ b3,
    float* __restrict__ out, float* __restrict__ nstate)
{
    const int w = threadIdx.x >> 5, lane = threadIdx.x & 31;
    const int r = blockIdx.x * 8 + w;
    const int n = r & (Nn - 1);
    const int c0 = lane * 8;
    const size_t o = (size_t)r * Cc + c0;

    float av[8], uv[8], pv[8], om[8];
    unpack8h(*reinterpret_cast<const uint4*>(&g_attnprojh[o]), av);
    unpack8h(*reinterpret_cast<const uint4*>(&g_updateh[o]), uv);
    {
        float4 a = *reinterpret_cast<const float4*>(&input_[o]);
        float4 b = *reinterpret_cast<const float4*>(&input_[o + 4]);
        float4 pa = *reinterpret_cast<const float4*>(&pos[(size_t)n * Cc + c0]);
        float4 pb = *reinterpret_cast<const float4*>(&pos[(size_t)n * Cc + c0 + 4]);
        float xin[8] = {a.x, a.y, a.z, a.w, b.x, b.y, b.z, b.w};
        float pp[8] = {pa.x, pa.y, pa.z, pa.w, pb.x, pb.y, pb.z, pb.w};
        #pragma unroll
        for (int i = 0; i < 8; i++) om[i] = xin[i] + pp[i] + av[i];
    }
    {
        float4 a = *reinterpret_cast<const float4*>(&prev[o]);
        float4 b = *reinterpret_cast<const float4*>(&prev[o + 4]);
        pv[0]=a.x; pv[1]=a.y; pv[2]=a.z; pv[3]=a.w;
        pv[4]=b.x; pv[5]=b.y; pv[6]=b.z; pv[7]=b.w;
    }
    // outputs
    *reinterpret_cast<float4*>(&out[o])     = make_float4(om[0], om[1], om[2], om[3]);
    *reinterpret_cast<float4*>(&out[o + 4]) = make_float4(om[4], om[5], om[6], om[7]);
    float ns[8];
    #pragma unroll
    for (int i = 0; i < 8; i++) ns[i] = pv[i] * (1.f - uv[i]) + av[i] * uv[i];
    *reinterpret_cast<float4*>(&nstate[o])     = make_float4(ns[0], ns[1], ns[2], ns[3]);
    *reinterpret_cast<float4*>(&nstate[o + 4]) = make_float4(ns[4], ns[5], ns[6], ns[7]);

    float s1 = 0.f, s2 = 0.f;
    #pragma unroll
    for (int i = 0; i < 8; i++) { s1 += om[i]; s2 += om[i] * om[i]; }
    float2 ss = warp_sum2(s1, s2);
    float mu = ss.x * (1.f / Cc);
    float rstd = rsqrtf(ss.y * (1.f / Cc) - mu * mu + 1e-5f);
    float hv[8];
    {
        float4 a = *reinterpret_cast<const float4*>(&w3[c0]);
        float4 b = *reinterpret_cast<const float4*>(&w3[c0 + 4]);
        float wv[8] = {a.x, a.y, a.z, a.w, b.x, b.y, b.z, b.w};
        a = *reinterpret_cast<const float4*>(&b3[c0]);
        b = *reinterpret_cast<const float4*>(&b3[c0 + 4]);
        float bv[8] = {a.x, a.y, a.z, a.w, b.x, b.y, b.z, b.w};
        #pragma unroll
        for (int i = 0; i < 8; i++) hv[i] = (om[i] - mu) * rstd * wv[i] + bv[i];
    }
    *reinterpret_cast<uint4*>(&g_hlnh[o]) = pack8h(hv);
}

// ---------------- launch ----------------------------------------------------
extern "C" void kernel_launch(void* const* d_in, const int* in_sizes, int n_in,
                              void* d_out, int out_size) {
    const float* input_   = (const float*)d_in[0];
    const float* prev     = (const float*)d_in[1];
    const float* pos      = (const float*)d_in[2];
    const float* n1w      = (const float*)d_in[3];
    const float* n1b      = (const float*)d_in[4];
    const float* n2w      = (const float*)d_in[5];
    const float* n2b      = (const float*)d_in[6];
    const float* n3w      = (const float*)d_in[7];
    const float* n3b      = (const float*)d_in[8];
    const float* qkv_iw   = (const float*)d_in[9];
    const float* qkv_sw   = (const float*)d_in[10];
    const float* proj_w   = (const float*)d_in[11];
    const float* proj_b   = (const float*)d_in[12];
    const float* gate_w   = (const float*)d_in[13];
    const float* gate_b   = (const float*)d_in[14];
    const float* fc1_w    = (const float*)d_in[15];
    const float* fc1_b    = (const float*)d_in[16];
    const float* fc2_w    = (const float*)d_in[17];
    const float* fc2_b    = (const float*)d_in[18];

    float* out    = (float*)d_out;
    float* nstate = out + (size_t)out_size / 2;

    __half *p_wh;
    __half *p_xlnh, *p_slnh, *p_xh, *p_sh, *p_qkvh, *p_attnpreh, *p_attnprojh,
           *p_updateh, *p_hlnh, *p_fc1h;
    cudaGetSymbolAddress((void**)&p_wh, g_wh);
    cudaGetSymbolAddress((void**)&p_xlnh, g_xlnh);
    cudaGetSymbolAddress((void**)&p_slnh, g_slnh);
    cudaGetSymbolAddress((void**)&p_xh, g_xh);
    cudaGetSymbolAddress((void**)&p_sh, g_sh);
    cudaGetSymbolAddress((void**)&p_qkvh, g_qkvh);
    cudaGetSymbolAddress((void**)&p_attnpreh, g_attnpreh);
    cudaGetSymbolAddress((void**)&p_attnprojh, g_attnprojh);
    cudaGetSymbolAddress((void**)&p_updateh, g_updateh);
    cudaGetSymbolAddress((void**)&p_hlnh, g_hlnh);
    cudaGetSymbolAddress((void**)&p_fc1h, g_fc1h);

    cudaFuncSetAttribute(mma_gemm_kernel,
                         cudaFuncAttributeMaxDynamicSharedMemorySize,
                         GEMM_SMEM_BYTES);

    // 0) all weights -> fp16 + zero g_kv (one kernel)
    w2h_all_kernel<<<1152, 256>>>(qkv_iw, qkv_sw, proj_w, gate_w, fc1_w, fc2_w);

    // 1) LN1 + LN2 + fp16 copies (warp per row)
    ln_pre_kernel<<<Mrows / 8, 256>>>(input_, prev, pos, n1w, n1b, n2w, n2b);

    // 2) qkv = x_ln @ Wi^T + s_ln @ Ws^T  (phi applied to q,k cols) fp16 out
    mma_gemm_kernel<<<dim3(768 / GBN, Mrows / GBM), 256, GEMM_SMEM_BYTES>>>(
        p_xlnh, p_slnh, p_wh + WOFF_QKVI, p_wh + WOFF_QKVS, nullptr, p_qkvh,
        3 * Cc, Cc, Cc, 3, 0, 1);

    // 3) kv[b,h,d,e]
    kv_kernel<<<dim3(Bb * Hh, 16), 256>>>();

    // 4) attn_pre = phi_q @ kv (warp per row-head, fp16 out)
    attn_kernel<<<Mrows, 256>>>();

    // 5) proj (fp16 out)
    mma_gemm_kernel<<<dim3(Cc / GBN, Mrows / GBM), 256, GEMM_SMEM_BYTES>>>(
        p_attnpreh, nullptr, p_wh + WOFF_PROJ, nullptr, proj_b, p_attnprojh,
        Cc, Cc, Cc, 0, 0, 1);

    // 6) gate: update = sigmoid([input_, prev] @ gate_w^T + gate_b) (fp16 out)
    mma_gemm_kernel<<<dim3(Cc / GBN, Mrows / GBM), 256, GEMM_SMEM_BYTES>>>(
        p_xh, p_sh, p_wh + WOFF_GATE, p_wh + WOFF_GATE + Cc, gate_b, p_updateh,
        Cc, Cc, 2 * Cc, 2, 0, 1);

    // 7) output_mid -> d_out, new_state, LN3 -> g_hlnh (warp per row)
    fuse_mid_kernel<<<Mrows / 8, 256>>>(input_, pos, prev, n3w, n3b, out, nstate);

    // 8) fc1 with exact-gelu epilogue (fp16 out)
    mma_gemm_kernel<<<dim3(HID / GBN, Mrows / GBM), 256, GEMM_SMEM_BYTES>>>(
        p_hlnh, nullptr, p_wh + WOFF_FC1, nullptr, fc1_b, p_fc1h,
        HID, Cc, Cc, 1, 0, 1);

    // 9) fc2, accumulate into output residual (fp32)
    mma_gemm_kernel<<<dim3(Cc / GBN, Mrows / GBM), 256, GEMM_SMEM_BYTES>>>(
        p_fc1h, nullptr, p_wh + WOFF_FC2, nullptr, fc2_b, out,
        Cc, HID, HID, 0, 1, 0);
}